// round 3
// baseline (speedup 1.0000x reference)
#include <cuda_runtime.h>
#include <cstddef>

#define IMH 1024
#define IMW 1024
#define SFRAMES 8
#define TR 32            // tile rows
#define TC 128           // tile cols
#define NTHREADS 512
#define GW (TC + 8)      // 136: gray tile width incl halo
#define GH (TR + 8)      // 40:  gray tile height incl halo
#define GN (GH * GW)     // 5440
#define NPREF ((GN + NTHREADS - 1) / NTHREADS)   // 11 items/thread

// padded index for tmp arrays: breaks stride-4 bank pattern (stride 5, coprime w/ 32)
__device__ __forceinline__ int padi(int i) { return i + (i >> 2); }

#define TPAD ((TR * GW) + ((TR * GW) >> 2))      // 5440 floats
#define SMEM_FLOATS (GN + 2 * TPAD + GN)          // sG + sTA + sTB + sOff(int)
#define SMEM_BYTES (SMEM_FLOATS * 4)

__device__ __forceinline__ int reflect101(int i, int n) {
    if (i < 0) i = -i;
    if (i >= n) i = 2 * n - 2 - i;
    return i;
}

extern "C" __global__ void __launch_bounds__(NTHREADS, 2)
lap_merge_kernel(const float* __restrict__ x, float* __restrict__ out)
{
    extern __shared__ float smem[];
    float* sG  = smem;                   // GN gray tile (+halo)
    float* sTA = smem + GN;              // padded TR*GW vertical-A
    float* sTB = sTA + TPAD;             // padded TR*GW vertical-B
    int*   sOff = (int*)(sTB + TPAD);    // GN frame-invariant gmem offsets

    const int tid = threadIdx.x;
    const int b   = blockIdx.z;
    const int hr0 = blockIdx.y * TR;
    const int wc0 = blockIdx.x * TC;
    const size_t HW = (size_t)IMH * IMW;
    const float ONE3 = 0.33333334f;

    // ---- Build frame-invariant offset table (once) ----
    for (int i = tid; i < GN; i += NTHREADS) {
        int r = i / GW;
        int c = i - r * GW;
        int gr = reflect101(hr0 - 4 + r, IMH);
        int gc = reflect101(wc0 - 4 + c, IMW);
        sOff[i] = gr * IMW + gc;
    }
    __syncthreads();

    // per-thread state: 8 px (2 groups of 4 consecutive cols)
    float bestLap[2][4];
    unsigned packedIdx = 0;              // 8 x 4-bit frame indices
#pragma unroll
    for (int it = 0; it < 2; it++)
#pragma unroll
        for (int o = 0; o < 4; o++) bestLap[it][o] = -3.0e38f;

    // ---- Prologue: prefetch frame 0 gray into registers ----
    float pv[NPREF];
    {
        const float* __restrict__ xf = x + ((size_t)(b * SFRAMES)) * 3 * HW;
#pragma unroll
        for (int k = 0; k < NPREF; k++) {
            int i = tid + k * NTHREADS;
            if (i < GN) {
                int off = sOff[i];
                pv[k] = (__ldg(xf + off) + __ldg(xf + off + HW) + __ldg(xf + off + 2 * HW)) * ONE3;
            }
        }
    }

    for (int s = 0; s < SFRAMES; s++) {
        // ---- Phase 1: store prefetched gray to smem ----
#pragma unroll
        for (int k = 0; k < NPREF; k++) {
            int i = tid + k * NTHREADS;
            if (i < GN) sG[i] = pv[k];
        }
        __syncthreads();

        // ---- Phase 2: vertical 9-tap A and B (4-row blocking) ----
        for (int t = tid; t < (TR / 4) * GW; t += NTHREADS) {
            int rg = t / GW;
            int c  = t - rg * GW;
            float g[12];
#pragma unroll
            for (int j = 0; j < 12; j++) g[j] = sG[(rg * 4 + j) * GW + c];
#pragma unroll
            for (int o = 0; o < 4; o++) {
                float p1 = g[o + 3] + g[o + 5];
                float p2 = g[o + 2] + g[o + 6];
                float p3 = g[o + 1] + g[o + 7];
                float p4 = g[o + 0] + g[o + 8];
                float ctr = g[o + 4];
                float tA =  4.375f * ctr + 3.5f  * p1 + 1.75f * p2 + 0.5f  * p3 + 0.0625f * p4;
                float tB = -0.625f * ctr - 0.25f * p1 + 0.25f * p2 + 0.25f * p3 + 0.0625f * p4;
                int oi = (rg * 4 + o) * GW + c;
                sTA[padi(oi)] = tA;
                sTB[padi(oi)] = tB;
            }
        }
        __syncthreads();

        // ---- Prefetch next frame's gray (overlaps phase 3 compute) ----
        if (s < SFRAMES - 1) {
            const float* __restrict__ xn = x + ((size_t)(b * SFRAMES + s + 1)) * 3 * HW;
#pragma unroll
            for (int k = 0; k < NPREF; k++) {
                int i = tid + k * NTHREADS;
                if (i < GN) {
                    int off = sOff[i];
                    pv[k] = (__ldg(xn + off) + __ldg(xn + off + HW) + __ldg(xn + off + 2 * HW)) * ONE3;
                }
            }
        }

        // ---- Phase 3: horizontal (B on tA + A on tB), branchless argmax ----
#pragma unroll
        for (int it = 0; it < 2; it++) {
            int t  = tid + it * NTHREADS;      // < TR*32 = 1024 exactly
            int r  = t >> 5;
            int cg = t & 31;
            int base = r * GW + cg * 4;
            float va[12], vb[12];
#pragma unroll
            for (int j = 0; j < 12; j++) {
                va[j] = sTA[padi(base + j)];
                vb[j] = sTB[padi(base + j)];
            }
#pragma unroll
            for (int o = 0; o < 4; o++) {
                float lap =
                      4.375f  * vb[o + 4] - 0.625f * va[o + 4]
                    + 3.5f    * (vb[o + 3] + vb[o + 5]) - 0.25f * (va[o + 3] + va[o + 5])
                    + 1.75f   * (vb[o + 2] + vb[o + 6]) + 0.25f * (va[o + 2] + va[o + 6])
                    + 0.5f    * (vb[o + 1] + vb[o + 7]) + 0.25f * (va[o + 1] + va[o + 7])
                    + 0.0625f * (vb[o + 0] + vb[o + 8]) + 0.0625f * (va[o + 0] + va[o + 8]);
                const int sh = (it * 4 + o) * 4;
                if (lap > bestLap[it][o]) {      // strict > == first-max (jnp.argmax) semantics
                    bestLap[it][o] = lap;
                    packedIdx = (packedIdx & ~(0xFu << sh)) | ((unsigned)s << sh);
                }
            }
        }
        __syncthreads();   // protect sTA/sTB (and sG) reuse by next frame
    }

    // ---- Epilogue: gather winning frame's RGB, write (b, c, h, w) ----
#pragma unroll
    for (int it = 0; it < 2; it++) {
        int t  = tid + it * NTHREADS;
        int r  = t >> 5;
        int cg = t & 31;
        int gr = hr0 + r;
        int gc = wc0 + cg * 4;
        size_t pix = (size_t)gr * IMW + gc;
        float R[4], G[4], B[4];
#pragma unroll
        for (int o = 0; o < 4; o++) {
            unsigned idx = (packedIdx >> ((it * 4 + o) * 4)) & 0xFu;
            const float* __restrict__ xw = x + ((size_t)(b * SFRAMES + idx)) * 3 * HW + pix + o;
            R[o] = __ldg(xw);
            G[o] = __ldg(xw + HW);
            B[o] = __ldg(xw + 2 * HW);
        }
        size_t obase = ((size_t)(b * 3) * IMH + gr) * IMW + gc;
        *reinterpret_cast<float4*>(out + obase)          = make_float4(R[0], R[1], R[2], R[3]);
        *reinterpret_cast<float4*>(out + obase + HW)     = make_float4(G[0], G[1], G[2], G[3]);
        *reinterpret_cast<float4*>(out + obase + 2 * HW) = make_float4(B[0], B[1], B[2], B[3]);
    }
}

extern "C" void kernel_launch(void* const* d_in, const int* in_sizes, int n_in,
                              void* d_out, int out_size)
{
    const float* x = (const float*)d_in[0];
    float* out = (float*)d_out;
    int nb = in_sizes[0] / (SFRAMES * 3 * IMH * IMW);   // = 4

    cudaFuncSetAttribute(lap_merge_kernel,
                         cudaFuncAttributeMaxDynamicSharedMemorySize, SMEM_BYTES);

    dim3 grid(IMW / TC, IMH / TR, nb);
    lap_merge_kernel<<<grid, NTHREADS, SMEM_BYTES>>>(x, out);
}

// round 4
// speedup vs baseline: 1.2317x; 1.2317x over previous
#include <cuda_runtime.h>
#include <cstddef>

#define IMH 1024
#define IMW 1024
#define SFRAMES 8
#define TR 32            // tile rows (output)
#define TC 128           // tile cols
#define NTHREADS 512
#define NW (NTHREADS / 32)       // 16 warps
#define GH (TR + 8)              // 40 rows incl vertical halo
#define RBW 136                  // per-warp row buffer width (128 + 8 halo)

// smem layout (floats): sHA[GH*TC] | sHB[GH*TC] | sRow[NW*RBW]
#define SMEM_FLOATS (2 * GH * TC + NW * RBW)
#define SMEM_BYTES  (SMEM_FLOATS * 4)

__device__ __forceinline__ int reflect101(int i, int n) {
    if (i < 0) i = -i;
    if (i >= n) i = 2 * n - 2 - i;
    return i;
}

extern "C" __global__ void __launch_bounds__(NTHREADS, 3)
lap_merge_kernel(const float* __restrict__ x, float* __restrict__ out)
{
    extern __shared__ float smem[];
    float* sHA  = smem;                    // horizontal A-filtered, GH x TC
    float* sHB  = smem + GH * TC;          // horizontal B-filtered, GH x TC
    float* sRow = smem + 2 * GH * TC;      // per-warp gray row buffers

    const int tid  = threadIdx.x;
    const int lane = tid & 31;
    const int warp = tid >> 5;
    const int b    = blockIdx.z;
    const int hr0  = blockIdx.y * TR;
    const int wc0  = blockIdx.x * TC;
    const size_t HW = (size_t)IMH * IMW;
    const float ONE3 = 0.33333334f;

    float* rowbuf = sRow + warp * RBW;

    // per-thread state: 8 px (2 groups of 4 consecutive cols), packed argmax
    float bestLap[2][4];
    unsigned packedIdx = 0;
#pragma unroll
    for (int it = 0; it < 2; it++)
#pragma unroll
        for (int o = 0; o < 4; o++) bestLap[it][o] = -3.0e38f;

    for (int s = 0; s < SFRAMES; s++) {
        const float* __restrict__ xf = x + ((size_t)(b * SFRAMES + s)) * 3 * HW;

        // ==== Phase 1: gray + horizontal 9-tap A/B, per-warp (no block barrier) ====
        for (int r = warp; r < GH; r += NW) {
            const int gr = reflect101(hr0 - 4 + r, IMH);
            const float* __restrict__ p0 = xf + (size_t)gr * IMW;
            const int c0 = wc0 + lane * 4;

            // main 128 cols: 3x float4 channel loads -> gray
            float4 ra = *reinterpret_cast<const float4*>(p0 + c0);
            float4 rb = *reinterpret_cast<const float4*>(p0 + HW + c0);
            float4 rc = *reinterpret_cast<const float4*>(p0 + 2 * HW + c0);
            float4 g4;
            g4.x = (ra.x + rb.x + rc.x) * ONE3;
            g4.y = (ra.y + rb.y + rc.y) * ONE3;
            g4.z = (ra.z + rb.z + rc.z) * ONE3;
            g4.w = (ra.w + rb.w + rc.w) * ONE3;
            *reinterpret_cast<float4*>(rowbuf + 4 + lane * 4) = g4;

            // halo: lane 0 -> left 4 cols, lane 31 -> right 4 cols
            if (lane == 0) {
                if (wc0 >= 4) {
                    float4 ha = *reinterpret_cast<const float4*>(p0 + wc0 - 4);
                    float4 hb = *reinterpret_cast<const float4*>(p0 + HW + wc0 - 4);
                    float4 hc = *reinterpret_cast<const float4*>(p0 + 2 * HW + wc0 - 4);
                    rowbuf[0] = (ha.x + hb.x + hc.x) * ONE3;
                    rowbuf[1] = (ha.y + hb.y + hc.y) * ONE3;
                    rowbuf[2] = (ha.z + hb.z + hc.z) * ONE3;
                    rowbuf[3] = (ha.w + hb.w + hc.w) * ONE3;
                } else {
#pragma unroll
                    for (int j = 0; j < 4; j++) {
                        int gc = reflect101(wc0 - 4 + j, IMW);
                        rowbuf[j] = (__ldg(p0 + gc) + __ldg(p0 + HW + gc)
                                     + __ldg(p0 + 2 * HW + gc)) * ONE3;
                    }
                }
            } else if (lane == 31) {
                int cR = wc0 + TC;
                if (cR + 3 < IMW) {
                    float4 ha = *reinterpret_cast<const float4*>(p0 + cR);
                    float4 hb = *reinterpret_cast<const float4*>(p0 + HW + cR);
                    float4 hc = *reinterpret_cast<const float4*>(p0 + 2 * HW + cR);
                    rowbuf[132] = (ha.x + hb.x + hc.x) * ONE3;
                    rowbuf[133] = (ha.y + hb.y + hc.y) * ONE3;
                    rowbuf[134] = (ha.z + hb.z + hc.z) * ONE3;
                    rowbuf[135] = (ha.w + hb.w + hc.w) * ONE3;
                } else {
#pragma unroll
                    for (int j = 0; j < 4; j++) {
                        int gc = reflect101(cR + j, IMW);
                        rowbuf[132 + j] = (__ldg(p0 + gc) + __ldg(p0 + HW + gc)
                                           + __ldg(p0 + 2 * HW + gc)) * ONE3;
                    }
                }
            }
            __syncwarp();

            // horizontal conv: window w[0..11] -> 4 outputs each of A- and B-filter
            float w[12];
#pragma unroll
            for (int j = 0; j < 12; j += 4)
                *reinterpret_cast<float4*>(&w[j]) =
                    *reinterpret_cast<const float4*>(rowbuf + lane * 4 + j);

            float4 hA4, hB4;
#pragma unroll
            for (int o = 0; o < 4; o++) {
                float p1 = w[o + 3] + w[o + 5];
                float p2 = w[o + 2] + w[o + 6];
                float p3 = w[o + 1] + w[o + 7];
                float p4 = w[o + 0] + w[o + 8];
                float ctr = w[o + 4];
                float tA =  4.375f * ctr + 3.5f  * p1 + 1.75f * p2 + 0.5f  * p3 + 0.0625f * p4;
                float tB = -0.625f * ctr - 0.25f * p1 + 0.25f * p2 + 0.25f * p3 + 0.0625f * p4;
                (&hA4.x)[o] = tA;
                (&hB4.x)[o] = tB;
            }
            *reinterpret_cast<float4*>(&sHA[r * TC + lane * 4]) = hA4;
            *reinterpret_cast<float4*>(&sHB[r * TC + lane * 4]) = hB4;
            __syncwarp();   // rowbuf reused next r by same warp
        }
        __syncthreads();

        // ==== Phase 2: vertical 9-tap (B on hA + A on hB), fold in argmax ====
        // wA = [.0625,.5,1.75,3.5,4.375,3.5,1.75,.5,.0625]
        // wB = [.0625,.25,.25,-.25,-.625,-.25,.25,.25,.0625]
        const float wAv[9] = {0.0625f, 0.5f, 1.75f, 3.5f, 4.375f, 3.5f, 1.75f, 0.5f, 0.0625f};
        const float wBv[9] = {0.0625f, 0.25f, 0.25f, -0.25f, -0.625f, -0.25f, 0.25f, 0.25f, 0.0625f};
#pragma unroll
        for (int it = 0; it < 2; it++) {
            const int t  = tid + it * NTHREADS;     // < 1024 exactly
            const int r  = t >> 5;
            const int cg = t & 31;
            const int base = r * TC + cg * 4;
            float acc0 = 0.f, acc1 = 0.f, acc2 = 0.f, acc3 = 0.f;
#pragma unroll
            for (int j = 0; j < 9; j++) {
                float4 ha = *reinterpret_cast<const float4*>(&sHA[base + j * TC]);
                float4 hb = *reinterpret_cast<const float4*>(&sHB[base + j * TC]);
                acc0 += wBv[j] * ha.x + wAv[j] * hb.x;
                acc1 += wBv[j] * ha.y + wAv[j] * hb.y;
                acc2 += wBv[j] * ha.z + wAv[j] * hb.z;
                acc3 += wBv[j] * ha.w + wAv[j] * hb.w;
            }
            float lap[4] = {acc0, acc1, acc2, acc3};
#pragma unroll
            for (int o = 0; o < 4; o++) {
                const int sh = (it * 4 + o) * 4;
                if (lap[o] > bestLap[it][o]) {   // strict > == first-max (jnp.argmax)
                    bestLap[it][o] = lap[o];
                    packedIdx = (packedIdx & ~(0xFu << sh)) | ((unsigned)s << sh);
                }
            }
        }
        __syncthreads();   // sHA/sHB reused by next frame
    }

    // ==== Epilogue: gather winning frame's RGB, write (b, c, h, w) ====
#pragma unroll
    for (int it = 0; it < 2; it++) {
        const int t  = tid + it * NTHREADS;
        const int r  = t >> 5;
        const int cg = t & 31;
        const int gr = hr0 + r;
        const int gc = wc0 + cg * 4;
        const size_t pix = (size_t)gr * IMW + gc;
        float R[4], G[4], B[4];
#pragma unroll
        for (int o = 0; o < 4; o++) {
            unsigned idx = (packedIdx >> ((it * 4 + o) * 4)) & 0xFu;
            const float* __restrict__ xw =
                x + ((size_t)(b * SFRAMES + idx)) * 3 * HW + pix + o;
            R[o] = __ldg(xw);
            G[o] = __ldg(xw + HW);
            B[o] = __ldg(xw + 2 * HW);
        }
        const size_t obase = ((size_t)(b * 3) * IMH + gr) * IMW + gc;
        *reinterpret_cast<float4*>(out + obase)          = make_float4(R[0], R[1], R[2], R[3]);
        *reinterpret_cast<float4*>(out + obase + HW)     = make_float4(G[0], G[1], G[2], G[3]);
        *reinterpret_cast<float4*>(out + obase + 2 * HW) = make_float4(B[0], B[1], B[2], B[3]);
    }
}

extern "C" void kernel_launch(void* const* d_in, const int* in_sizes, int n_in,
                              void* d_out, int out_size)
{
    const float* x = (const float*)d_in[0];
    float* out = (float*)d_out;
    int nb = in_sizes[0] / (SFRAMES * 3 * IMH * IMW);   // = 4

    cudaFuncSetAttribute(lap_merge_kernel,
                         cudaFuncAttributeMaxDynamicSharedMemorySize, SMEM_BYTES);

    dim3 grid(IMW / TC, IMH / TR, nb);
    lap_merge_kernel<<<grid, NTHREADS, SMEM_BYTES>>>(x, out);
}